// round 1
// baseline (speedup 1.0000x reference)
#include <cuda_runtime.h>

#define B_ROWS 8192
#define D_DIM  128
#define C_CLS  100
#define MARGIN 0.3f
#define NBLK   1024   // 8 rows (warps) per 256-thread block

__device__ int   g_is64;
__device__ float g_partials[NBLK];

// Detect whether index buffers are int64 (JAX x64 on) or int32 (default).
// For int64 little-endian values < 2^31, every odd 32-bit word is 0.
// For int32, odd words are random targets in [0,100) -> essentially never all zero.
__global__ void detect_idx_width_kernel(const unsigned int* __restrict__ targets_words) {
    __shared__ int found_nonzero;
    if (threadIdx.x == 0) found_nonzero = 0;
    __syncthreads();
    for (int i = threadIdx.x; i < B_ROWS / 2; i += blockDim.x) {
        if (targets_words[2 * i + 1] != 0u) found_nonzero = 1;
    }
    __syncthreads();
    if (threadIdx.x == 0) g_is64 = found_nonzero ? 0 : 1;
}

__device__ __forceinline__ int load_idx(const void* p, int i, int is64) {
    if (is64) return (int)((const long long*)p)[i];
    return ((const int*)p)[i];
}

__global__ __launch_bounds__(256, 8)
void triplet_rows_kernel(const float* __restrict__ x,
                         const void*  __restrict__ targets,
                         const void*  __restrict__ ixs,
                         const float* __restrict__ brdf) {
    const int is64 = g_is64;
    const int warp = threadIdx.x >> 5;
    const int lane = threadIdx.x & 31;
    const int row  = blockIdx.x * 8 + warp;   // grid exactly covers B_ROWS

    const int i0 = load_idx(ixs, 2 * row,     is64);
    const int i1 = load_idx(ixs, 2 * row + 1, is64);

    const float4* xa = (const float4*)(x + (size_t)row * D_DIM);
    const float4* xb0 = (const float4*)(x + (size_t)i0 * D_DIM);
    const float4* xb1 = (const float4*)(x + (size_t)i1 * D_DIM);

    float4 a  = xa[lane];
    float4 p0 = xb0[lane];
    float4 p1 = xb1[lane];

    float dx, s0, s1;
    dx = a.x - p0.x; s0  = dx * dx;
    dx = a.y - p0.y; s0 += dx * dx;
    dx = a.z - p0.z; s0 += dx * dx;
    dx = a.w - p0.w; s0 += dx * dx;
    dx = a.x - p1.x; s1  = dx * dx;
    dx = a.y - p1.y; s1 += dx * dx;
    dx = a.z - p1.z; s1 += dx * dx;
    dx = a.w - p1.w; s1 += dx * dx;

    #pragma unroll
    for (int off = 16; off > 0; off >>= 1) {
        s0 += __shfl_xor_sync(0xFFFFFFFFu, s0, off);
        s1 += __shfl_xor_sync(0xFFFFFFFFu, s1, off);
    }

    __shared__ float wsum[8];
    if (lane == 0) {
        float d0 = sqrtf(fmaxf(s0, 1e-12f));
        float d1 = sqrtf(fmaxf(s1, 1e-12f));
        int tb = load_idx(targets, row, is64);
        int t0 = load_idx(targets, i0,  is64);
        int t1 = load_idx(targets, i1,  is64);
        float md1 = brdf[tb * C_CLS + t0];
        float md2 = brdf[tb * C_CLS + t1];
        float dist_ap, dist_an;
        if (md1 < md2) { dist_ap = d0; dist_an = d1; }
        else           { dist_ap = d1; dist_an = d0; }
        wsum[warp] = fmaxf(dist_ap - dist_an + MARGIN, 0.0f);
    }
    __syncthreads();
    if (threadIdx.x == 0) {
        float t = 0.0f;
        #pragma unroll
        for (int w = 0; w < 8; w++) t += wsum[w];
        g_partials[blockIdx.x] = t;
    }
}

__global__ __launch_bounds__(256)
void finalize_kernel(float* __restrict__ out) {
    __shared__ float s[256];
    float t = 0.0f;
    for (int i = threadIdx.x; i < NBLK; i += 256) t += g_partials[i];
    s[threadIdx.x] = t;
    __syncthreads();
    #pragma unroll
    for (int off = 128; off > 0; off >>= 1) {
        if (threadIdx.x < off) s[threadIdx.x] += s[threadIdx.x + off];
        __syncthreads();
    }
    if (threadIdx.x == 0) out[0] = s[0] * (1.0f / (float)B_ROWS);
}

extern "C" void kernel_launch(void* const* d_in, const int* in_sizes, int n_in,
                              void* d_out, int out_size) {
    const float* x       = (const float*)d_in[0];  // inputs   [8192,128] f32
    const void*  targets = d_in[1];                // targets  [8192]     i32/i64
    const void*  ixs     = d_in[2];                // ixs      [8192,2]   i32/i64
    const float* brdf    = (const float*)d_in[3];  // brdf     [100,100]  f32
    float*       out     = (float*)d_out;

    detect_idx_width_kernel<<<1, 256>>>((const unsigned int*)targets);
    triplet_rows_kernel<<<NBLK, 256>>>(x, targets, ixs, brdf);
    finalize_kernel<<<1, 256>>>(out);
}

// round 2
// speedup vs baseline: 1.5111x; 1.5111x over previous
#include <cuda_runtime.h>

#define B_ROWS 8192
#define D_DIM  128
#define C_CLS  100
#define MARGIN 0.3f
#define NBLK   1024   // 8 rows (warps) per 256-thread block

__device__ float        g_partials[NBLK];
__device__ unsigned int g_done;   // zero at module load; reset by last block each run

__device__ __forceinline__ int load_idx(const void* p, int i, int is64) {
    if (is64) return (int)((const long long*)p)[i];
    return ((const int*)p)[i];
}

__global__ __launch_bounds__(256, 8)
void triplet_fused_kernel(const float* __restrict__ x,
                          const void*  __restrict__ targets,
                          const void*  __restrict__ ixs,
                          const float* __restrict__ brdf,
                          float*       __restrict__ out) {
    const int warp = threadIdx.x >> 5;
    const int lane = threadIdx.x & 31;
    const int row  = blockIdx.x * 8 + warp;   // grid exactly covers B_ROWS

    // ---- inline index-width detection (per warp, no barrier) ----
    // int64 little-endian with values < 2^31: odd 32-bit words are all zero.
    // int32: odd words are targets[1..63] in [0,100) -> P(all 32 zero) ~ 1e-64.
    unsigned int hw = ((const unsigned int*)targets)[2 * lane + 1];
    const int is64 = (__ballot_sync(0xFFFFFFFFu, hw != 0u) == 0u);

    const int i0 = load_idx(ixs, 2 * row,     is64);
    const int i1 = load_idx(ixs, 2 * row + 1, is64);

    const float4* xa  = (const float4*)(x + (size_t)row * D_DIM);
    const float4* xb0 = (const float4*)(x + (size_t)i0 * D_DIM);
    const float4* xb1 = (const float4*)(x + (size_t)i1 * D_DIM);

    float4 a  = xa[lane];
    float4 p0 = xb0[lane];
    float4 p1 = xb1[lane];

    float dx, s0, s1;
    dx = a.x - p0.x; s0  = dx * dx;
    dx = a.y - p0.y; s0 += dx * dx;
    dx = a.z - p0.z; s0 += dx * dx;
    dx = a.w - p0.w; s0 += dx * dx;
    dx = a.x - p1.x; s1  = dx * dx;
    dx = a.y - p1.y; s1 += dx * dx;
    dx = a.z - p1.z; s1 += dx * dx;
    dx = a.w - p1.w; s1 += dx * dx;

    #pragma unroll
    for (int off = 16; off > 0; off >>= 1) {
        s0 += __shfl_xor_sync(0xFFFFFFFFu, s0, off);
        s1 += __shfl_xor_sync(0xFFFFFFFFu, s1, off);
    }

    __shared__ float wsum[8];
    __shared__ int   s_last;
    if (lane == 0) {
        float d0 = sqrtf(fmaxf(s0, 1e-12f));
        float d1 = sqrtf(fmaxf(s1, 1e-12f));
        int tb = load_idx(targets, row, is64);
        int t0 = load_idx(targets, i0,  is64);
        int t1 = load_idx(targets, i1,  is64);
        float md1 = brdf[tb * C_CLS + t0];
        float md2 = brdf[tb * C_CLS + t1];
        float dist_ap, dist_an;
        if (md1 < md2) { dist_ap = d0; dist_an = d1; }
        else           { dist_ap = d1; dist_an = d0; }
        wsum[warp] = fmaxf(dist_ap - dist_an + MARGIN, 0.0f);
    }
    __syncthreads();

    if (threadIdx.x == 0) {
        float t = 0.0f;
        #pragma unroll
        for (int w = 0; w < 8; w++) t += wsum[w];
        g_partials[blockIdx.x] = t;
        __threadfence();
        unsigned int prev = atomicAdd(&g_done, 1u);
        s_last = (prev == (unsigned int)(gridDim.x - 1));
    }
    __syncthreads();

    // ---- last block performs the deterministic final reduction ----
    if (s_last) {
        __shared__ float s[256];
        float t = 0.0f;
        for (int i = threadIdx.x; i < NBLK; i += 256) t += g_partials[i];
        s[threadIdx.x] = t;
        __syncthreads();
        #pragma unroll
        for (int off = 128; off > 0; off >>= 1) {
            if (threadIdx.x < off) s[threadIdx.x] += s[threadIdx.x + off];
            __syncthreads();
        }
        if (threadIdx.x == 0) {
            out[0] = s[0] * (1.0f / (float)B_ROWS);
            g_done = 0u;   // reset for next graph replay
        }
    }
}

extern "C" void kernel_launch(void* const* d_in, const int* in_sizes, int n_in,
                              void* d_out, int out_size) {
    const float* x       = (const float*)d_in[0];  // inputs   [8192,128] f32
    const void*  targets = d_in[1];                // targets  [8192]     i32/i64
    const void*  ixs     = d_in[2];                // ixs      [8192,2]   i32/i64
    const float* brdf    = (const float*)d_in[3];  // brdf     [100,100]  f32
    float*       out     = (float*)d_out;

    triplet_fused_kernel<<<NBLK, 256>>>(x, targets, ixs, brdf, out);
}